// round 14
// baseline (speedup 1.0000x reference)
#include <cuda_runtime.h>
#include <cuda_bf16.h>
#include <cstdint>
#include <cstddef>
#include <math.h>

// Problem dims
#define Bb 8
#define Ss 2048
#define Hh 1024
#define Nst 256
#define Mm (Bb * Ss)        // 16384

// GEMM tiling: CTA 128x256x32, 8 warps of 64x64, cp.async 4-stage
#define BM 128
#define BN 256
#define BK 32
#define ASTR 40                          // smem row stride in bf16 (80 B)
#define A_STAGE_B (128 * ASTR * 2)       // 10240 B
#define B_STAGE_B (256 * ASTR * 2)       // 20480 B
#define STAGE_B   (A_STAGE_B + B_STAGE_B)// 30720 B
#define NSTG 4
#define SMEM_TOTAL (NSTG * STAGE_B)      // 122880 B

// ---------------------------------------------------------------------------
// Scratch. Row-major. A-side K3 regions [hi|lo|hi]; W-side [hi|hi|lo].
// ---------------------------------------------------------------------------
__device__ __align__(256) __nv_bfloat16 g_x3 [(size_t)Mm * 3 * Hh];
__device__ __align__(256) __nv_bfloat16 g_wg3[(size_t)512 * 3 * Hh];
__device__ __align__(256) float         g_uv [(size_t)Mm * 512];
__device__ __align__(256) __nv_bfloat16 g_s3 [(size_t)Mm * 3 * Nst];
__device__ __align__(256) __nv_bfloat16 g_wc3[(size_t)Hh * 3 * Nst];
__device__ __align__(256) float         g_h  [(size_t)Mm * Hh];
__device__ __align__(256) __nv_bfloat16 g_hn3[(size_t)Mm * 3 * Hh];
__device__ __align__(256) __nv_bfloat16 g_wo3[(size_t)Hh * 3 * Hh];

// ---------------------------------------------------------------------------
// helpers
// ---------------------------------------------------------------------------
__device__ __forceinline__ uint32_t cvta_smem(const void* p) {
    uint32_t a;
    asm("{ .reg .u64 t; cvta.to.shared.u64 t, %1; cvt.u32.u64 %0, t; }"
        : "=r"(a) : "l"(p));
    return a;
}
__device__ __forceinline__ void ldsm4(uint32_t& r0, uint32_t& r1,
                                      uint32_t& r2, uint32_t& r3, uint32_t addr) {
    asm volatile("ldmatrix.sync.aligned.m8n8.x4.shared.b16 {%0,%1,%2,%3}, [%4];"
                 : "=r"(r0), "=r"(r1), "=r"(r2), "=r"(r3) : "r"(addr));
}
__device__ __forceinline__ void mma16816(float* d, const uint32_t* a, const uint32_t* b) {
    asm volatile(
        "mma.sync.aligned.m16n8k16.row.col.f32.bf16.bf16.f32 "
        "{%0,%1,%2,%3}, {%4,%5,%6,%7}, {%8,%9}, {%0,%1,%2,%3};"
        : "+f"(d[0]), "+f"(d[1]), "+f"(d[2]), "+f"(d[3])
        : "r"(a[0]), "r"(a[1]), "r"(a[2]), "r"(a[3]), "r"(b[0]), "r"(b[1]));
}
__device__ __forceinline__ void cpasync16(uint32_t dst, const void* src) {
    asm volatile("cp.async.cg.shared.global [%0], [%1], 16;"
                 :: "r"(dst), "l"(src));
}
__device__ __forceinline__ void cp_commit() {
    asm volatile("cp.async.commit_group;" ::: "memory");
}
__device__ __forceinline__ void cp_wait2() {
    asm volatile("cp.async.wait_group 2;" ::: "memory");
}
__device__ __forceinline__ void split_bf16(float v, __nv_bfloat16& hi, __nv_bfloat16& lo) {
    hi = __float2bfloat16(v);
    lo = __float2bfloat16(v - __bfloat162float(hi));
}

// ---------------------------------------------------------------------------
// Conversion: f32 [rows, K] -> bf16 hi/lo split [rows, 3K].
// ---------------------------------------------------------------------------
template <int DSTSEL, int IS_W, int K>
__global__ __launch_bounds__(256)
void conv_kernel(const float* __restrict__ src, int row_base)
{
    __nv_bfloat16* dst = (DSTSEL == 0) ? g_x3 : (DSTSEL == 1) ? g_wg3
                       : (DSTSEL == 2) ? g_wc3 : g_wo3;
    const size_t i = (size_t)blockIdx.x * 256 + threadIdx.x;
    const float4 v = ((const float4*)src)[i];
    const size_t e = i * 4;
    const size_t row = e / K;
    const int k = (int)(e - row * K);

    const float f[4] = { v.x, v.y, v.z, v.w };
    __nv_bfloat16 hi[4], lo[4];
#pragma unroll
    for (int j = 0; j < 4; j++) split_bf16(f[j], hi[j], lo[j]);

    __nv_bfloat16* base = dst + (row_base + row) * (size_t)(3 * K) + k;
    *(uint2*)(base)         = *(const uint2*)hi;
    *(uint2*)(base + K)     = IS_W ? *(const uint2*)hi : *(const uint2*)lo;
    *(uint2*)(base + 2 * K) = IS_W ? *(const uint2*)lo : *(const uint2*)hi;
}

// ---------------------------------------------------------------------------
// Pipelined warp-MMA bf16 GEMM with fragment double-buffering.
//   MODE 0: g_uv (ldc 512); MODE 1: g_h = acc+(D+1)*X (ldc 1024);
//   MODE 2: C_ext = acc + bias (ldc 1024)
// ---------------------------------------------------------------------------
template <int MODE>
__global__ __launch_bounds__(256, 1)
void tgemm(float* __restrict__ C_ext, const float* __restrict__ bias,
           const float* __restrict__ X, const float* __restrict__ Dv, int K3)
{
    extern __shared__ __align__(128) char smem[];
    const uint32_t sb = cvta_smem(smem);

    const __nv_bfloat16* A = (MODE == 0) ? g_x3  : (MODE == 1) ? g_s3  : g_hn3;
    const __nv_bfloat16* W = (MODE == 0) ? g_wg3 : (MODE == 1) ? g_wc3 : g_wo3;
    float* C = (MODE == 0) ? g_uv : (MODE == 1) ? g_h : C_ext;
    const int ldc = (MODE == 0) ? 512 : 1024;

    const int tid = threadIdx.x, lane = tid & 31, wid = tid >> 5;
    const int wm = wid & 1, wn = wid >> 1;          // 2 x 4 warp grid
    const int m0 = blockIdx.y * BM, n0 = blockIdx.x * BN;

    // cp.async mapping
    const int arow = tid >> 2;
    const int aseg = tid & 3;
    const __nv_bfloat16* Ag = A + (size_t)(m0 + arow) * K3 + aseg * 8;
    const __nv_bfloat16* Wg = W + (size_t)(n0 + arow) * K3 + aseg * 8;
    const size_t a64 = (size_t)64 * K3;
    const uint32_t aDst  = sb + (arow * ASTR + aseg * 8) * 2;
    const uint32_t aDst2 = aDst + 64 * ASTR * 2;

    const int NKT = K3 >> 5;

    auto issue = [&](int s, int kt) {
        const uint32_t so = (uint32_t)(s * STAGE_B);
        const size_t ko = (size_t)kt * 32;
        cpasync16(aDst + so, Ag + ko);
        cpasync16(aDst2 + so, Ag + a64 + ko);
        const uint32_t bo = so + A_STAGE_B;
#pragma unroll
        for (int t = 0; t < 4; t++)
            cpasync16(aDst + bo + (uint32_t)(t * 64 * ASTR * 2),
                      Wg + (size_t)t * a64 + ko);
    };

#pragma unroll
    for (int s = 0; s < 3; s++) { issue(s, s); cp_commit(); }

    float acc[4][8][4];
#pragma unroll
    for (int i = 0; i < 4; i++)
#pragma unroll
        for (int j = 0; j < 8; j++)
#pragma unroll
            for (int q = 0; q < 4; q++) acc[i][j][q] = 0.f;

    const int lrow = lane & 15;
    const int lcol = (lane >> 4) << 3;
    const uint32_t aBase = sb + ((wm * 64 + lrow) * ASTR + lcol) * 2;
    const uint32_t bBase = sb + A_STAGE_B + ((wn * 64 + lrow) * ASTR + lcol) * 2;

    // fragment double buffers
    uint32_t fa[2][4][4], fb[2][8][2];

    auto load_frags = [&](int buf, int s, int h) {
        const uint32_t so = (uint32_t)(s * STAGE_B);
        const uint32_t aS = aBase + so;
        const uint32_t bS = bBase + so;
#pragma unroll
        for (int i = 0; i < 4; i++)
            ldsm4(fa[buf][i][0], fa[buf][i][1], fa[buf][i][2], fa[buf][i][3],
                  aS + (i * 16 * ASTR + h * 16) * 2);
#pragma unroll
        for (int jj = 0; jj < 4; jj++) {
            uint32_t r0, r1, r2, r3;
            ldsm4(r0, r1, r2, r3, bS + (jj * 16 * ASTR + h * 16) * 2);
            fb[buf][2 * jj][0] = r0;     fb[buf][2 * jj][1] = r2;
            fb[buf][2 * jj + 1][0] = r1; fb[buf][2 * jj + 1][1] = r3;
        }
    };
    auto mma_frags = [&](int buf) {
#pragma unroll
        for (int i = 0; i < 4; i++)
#pragma unroll
            for (int j = 0; j < 8; j++)
                mma16816(acc[i][j], fa[buf][i], fb[buf][j]);
    };

    // preamble: stage 0 ready, load (kt0, h0)
    cp_wait2();
    __syncthreads();
    load_frags(0, 0, 0);

    for (int kt = 0; kt < NKT; kt++) {
        const int s = kt & 3;
        // prefetch h=1 frags of this tile, then crunch h=0
        load_frags(1, s, 1);
        mma_frags(0);
        if (kt + 1 < NKT) {
            // refill stage consumed at kt-1 (safe: bar of iter kt-1 passed)
            if (kt + 3 < NKT) issue((kt + 3) & 3, kt + 3);
            cp_commit();
            cp_wait2();
            __syncthreads();
            // prefetch next tile h=0, then crunch h=1
            load_frags(0, (kt + 1) & 3, 0);
        }
        mma_frags(1);
    }

    // epilogue
#pragma unroll
    for (int i = 0; i < 4; i++) {
        const int r = m0 + wm * 64 + i * 16 + (lane >> 2);
#pragma unroll
        for (int j = 0; j < 8; j++) {
            const int c = n0 + wn * 64 + j * 8 + (lane & 3) * 2;
            float2 v0 = make_float2(acc[i][j][0], acc[i][j][1]);
            float2 v1 = make_float2(acc[i][j][2], acc[i][j][3]);
            if (MODE == 1) {
                const float2 dv = *(const float2*)(Dv + c);
                const float2 x0 = *(const float2*)(X + (size_t)r * 1024 + c);
                const float2 x1 = *(const float2*)(X + (size_t)(r + 8) * 1024 + c);
                v0.x += (dv.x + 1.0f) * x0.x;  v0.y += (dv.y + 1.0f) * x0.y;
                v1.x += (dv.x + 1.0f) * x1.x;  v1.y += (dv.y + 1.0f) * x1.y;
            } else if (MODE == 2) {
                const float2 bv = *(const float2*)(bias + c);
                v0.x += bv.x; v0.y += bv.y;
                v1.x += bv.x; v1.y += bv.y;
            }
            *(float2*)&C[(size_t)r * ldc + c]       = v0;
            *(float2*)&C[(size_t)(r + 8) * ldc + c] = v1;
        }
    }
}

// ---------------------------------------------------------------------------
// Fused gate + scan + state split -> g_s3 (hi|lo|hi), final_state
// ---------------------------------------------------------------------------
__global__ __launch_bounds__(256)
void scan_kernel(const float* __restrict__ state0,
                 const float* __restrict__ A_log,
                 const float* __restrict__ gate_b,
                 float* __restrict__ final_state)
{
    const int chain = blockIdx.x * 256 + threadIdx.x;
    const int b = chain >> 8;
    const int n = chain & (Nst - 1);

    float Av = expf(A_log[n]);
    Av = fminf(fmaxf(Av, 0.5f), 0.99f);
    const float gb = gate_b[n];

    float s = state0[b * Nst + n];
    const float* uvp = g_uv + (size_t)b * Ss * 512 + n;
    __nv_bfloat16* sp = g_s3 + (size_t)b * Ss * (3 * Nst) + n;

#pragma unroll 4
    for (int t = 0; t < Ss; t++) {
        const float gl = uvp[(size_t)t * 512] + gb;
        const float ub = uvp[(size_t)t * 512 + 256];
        float sg = 1.0f / (1.0f + expf(-gl));
        sg = fminf(fmaxf(sg, 0.0f), 1.0f);
        s = fminf(fmaxf(fmaf(Av, s, sg * ub), -10.0f), 10.0f);
        __nv_bfloat16 hi, lo;
        split_bf16(s, hi, lo);
        sp[(size_t)t * 768]       = hi;
        sp[(size_t)t * 768 + 256] = lo;
        sp[(size_t)t * 768 + 512] = hi;
    }
    final_state[b * Nst + n] = s;
}

// ---------------------------------------------------------------------------
// LayerNorm (single pass, shuffle reductions) + hi/lo split -> g_hn3
// ---------------------------------------------------------------------------
__global__ __launch_bounds__(256)
void ln_kernel(const float* __restrict__ g, const float* __restrict__ bta)
{
    __shared__ float psum[8], psq[8], bcast[2];
    const int row = blockIdx.x;
    const int t = threadIdx.x;
    const int lane = t & 31, wd = t >> 5;
    const float* hp = g_h + (size_t)row * Hh;

    float4 v = *(const float4*)(hp + (t << 2));
    float sm = v.x + v.y + v.z + v.w;
    float sq = v.x * v.x + v.y * v.y + v.z * v.z + v.w * v.w;

#pragma unroll
    for (int off = 16; off; off >>= 1) {
        sm += __shfl_xor_sync(0xffffffffu, sm, off);
        sq += __shfl_xor_sync(0xffffffffu, sq, off);
    }
    if (lane == 0) { psum[wd] = sm; psq[wd] = sq; }
    __syncthreads();
    if (wd == 0) {
        float a = (lane < 8) ? psum[lane] : 0.f;
        float b = (lane < 8) ? psq[lane] : 0.f;
#pragma unroll
        for (int off = 4; off; off >>= 1) {
            a += __shfl_xor_sync(0xffffffffu, a, off);
            b += __shfl_xor_sync(0xffffffffu, b, off);
        }
        if (lane == 0) {
            const float mu = a * (1.0f / Hh);
            const float var = b * (1.0f / Hh) - mu * mu;
            bcast[0] = mu;
            bcast[1] = rsqrtf(var + 1e-5f);
        }
    }
    __syncthreads();
    const float mu = bcast[0], inv = bcast[1];

    const int c = t << 2;
    float o[4];
    o[0] = (v.x - mu) * inv * g[c + 0] + bta[c + 0];
    o[1] = (v.y - mu) * inv * g[c + 1] + bta[c + 1];
    o[2] = (v.z - mu) * inv * g[c + 2] + bta[c + 2];
    o[3] = (v.w - mu) * inv * g[c + 3] + bta[c + 3];

    __nv_bfloat16 hi[4], lo[4];
#pragma unroll
    for (int j = 0; j < 4; j++) split_bf16(o[j], hi[j], lo[j]);

    __nv_bfloat16* base = g_hn3 + (size_t)row * (3 * Hh) + c;
    *(uint2*)(base)          = *(const uint2*)hi;
    *(uint2*)(base + Hh)     = *(const uint2*)lo;
    *(uint2*)(base + 2 * Hh) = *(const uint2*)hi;
}

// ---------------------------------------------------------------------------
// Launch
// ---------------------------------------------------------------------------
extern "C" void kernel_launch(void* const* d_in, const int* in_sizes, int n_in,
                              void* d_out, int out_size)
{
    const float* x      = (const float*)d_in[0];
    const float* state0 = (const float*)d_in[1];
    const float* A_log  = (const float*)d_in[2];
    const float* B_w    = (const float*)d_in[3];
    const float* C_w    = (const float*)d_in[4];
    const float* Dv     = (const float*)d_in[5];
    const float* gate_w = (const float*)d_in[6];
    const float* gate_b = (const float*)d_in[7];
    const float* out_w  = (const float*)d_in[8];
    const float* out_b  = (const float*)d_in[9];
    const float* ln_g   = (const float*)d_in[10];
    const float* ln_b   = (const float*)d_in[11];

    float* out = (float*)d_out;
    float* final_state = out + (size_t)Mm * Hh;

    cudaFuncSetAttribute(tgemm<0>, cudaFuncAttributeMaxDynamicSharedMemorySize, SMEM_TOTAL);
    cudaFuncSetAttribute(tgemm<1>, cudaFuncAttributeMaxDynamicSharedMemorySize, SMEM_TOTAL);
    cudaFuncSetAttribute(tgemm<2>, cudaFuncAttributeMaxDynamicSharedMemorySize, SMEM_TOTAL);

    // 1) conversions
    conv_kernel<0, 0, 1024><<<Mm, 256>>>(x, 0);
    conv_kernel<1, 1, 1024><<<256, 256>>>(gate_w, 0);
    conv_kernel<1, 1, 1024><<<256, 256>>>(B_w, 256);

    // 2) GEMM0: g_uv[16384, 512]   (K3 = 3072)
    tgemm<0><<<dim3(512 / BN, Mm / BM), 256, SMEM_TOTAL>>>(
        nullptr, nullptr, nullptr, nullptr, 3 * Hh);

    // 3) fused gate + scan + split
    scan_kernel<<<(Bb * Nst) / 256, 256>>>(state0, A_log, gate_b, final_state);

    // 4) GEMM1: g_h = s3 @ wc3^T + (D+1)*x   (K3 = 768)
    conv_kernel<2, 1, 256><<<256, 256>>>(C_w, 0);
    tgemm<1><<<dim3(Hh / BN, Mm / BM), 256, SMEM_TOTAL>>>(
        nullptr, nullptr, x, Dv, 3 * Nst);

    // 5) LN + split
    ln_kernel<<<Mm, 256>>>(ln_g, ln_b);

    // 6) GEMM2: out = hn3 @ wo3^T + out_b    (K3 = 3072)
    conv_kernel<3, 1, 1024><<<1024, 256>>>(out_w, 0);
    tgemm<2><<<dim3(Hh / BN, Mm / BM), 256, SMEM_TOTAL>>>(
        out, out_b, nullptr, nullptr, 3 * Hh);
}

// round 15
// speedup vs baseline: 1.0529x; 1.0529x over previous
#include <cuda_runtime.h>
#include <cuda_bf16.h>
#include <cstdint>
#include <cstddef>
#include <math.h>

// Problem dims
#define Bb 8
#define Ss 2048
#define Hh 1024
#define Nst 256
#define Mm (Bb * Ss)        // 16384

// GEMM tiling: CTA 128x256x32, 16 warps of 64x32, cp.async 4-stage
#define BM 128
#define BN 256
#define BK 32
#define ASTR 40                          // smem row stride in bf16 (80 B)
#define A_STAGE_B (128 * ASTR * 2)       // 10240 B
#define B_STAGE_B (256 * ASTR * 2)       // 20480 B
#define STAGE_B   (A_STAGE_B + B_STAGE_B)// 30720 B
#define NSTG 4
#define SMEM_TOTAL (NSTG * STAGE_B)      // 122880 B

// ---------------------------------------------------------------------------
// Scratch. Row-major. A-side K3 regions [hi|lo|hi]; W-side [hi|hi|lo].
// ---------------------------------------------------------------------------
__device__ __align__(256) __nv_bfloat16 g_x3 [(size_t)Mm * 3 * Hh];
__device__ __align__(256) __nv_bfloat16 g_wg3[(size_t)512 * 3 * Hh];
__device__ __align__(256) float         g_uv [(size_t)Mm * 512];
__device__ __align__(256) __nv_bfloat16 g_s3 [(size_t)Mm * 3 * Nst];
__device__ __align__(256) __nv_bfloat16 g_wc3[(size_t)Hh * 3 * Nst];
__device__ __align__(256) float         g_h  [(size_t)Mm * Hh];
__device__ __align__(256) __nv_bfloat16 g_hn3[(size_t)Mm * 3 * Hh];
__device__ __align__(256) __nv_bfloat16 g_wo3[(size_t)Hh * 3 * Hh];

// ---------------------------------------------------------------------------
// helpers
// ---------------------------------------------------------------------------
__device__ __forceinline__ uint32_t cvta_smem(const void* p) {
    uint32_t a;
    asm("{ .reg .u64 t; cvta.to.shared.u64 t, %1; cvt.u32.u64 %0, t; }"
        : "=r"(a) : "l"(p));
    return a;
}
__device__ __forceinline__ void ldsm4(uint32_t& r0, uint32_t& r1,
                                      uint32_t& r2, uint32_t& r3, uint32_t addr) {
    asm volatile("ldmatrix.sync.aligned.m8n8.x4.shared.b16 {%0,%1,%2,%3}, [%4];"
                 : "=r"(r0), "=r"(r1), "=r"(r2), "=r"(r3) : "r"(addr));
}
__device__ __forceinline__ void mma16816(float* d, const uint32_t* a, const uint32_t* b) {
    asm volatile(
        "mma.sync.aligned.m16n8k16.row.col.f32.bf16.bf16.f32 "
        "{%0,%1,%2,%3}, {%4,%5,%6,%7}, {%8,%9}, {%0,%1,%2,%3};"
        : "+f"(d[0]), "+f"(d[1]), "+f"(d[2]), "+f"(d[3])
        : "r"(a[0]), "r"(a[1]), "r"(a[2]), "r"(a[3]), "r"(b[0]), "r"(b[1]));
}
__device__ __forceinline__ void cpasync16(uint32_t dst, const void* src) {
    asm volatile("cp.async.cg.shared.global [%0], [%1], 16;"
                 :: "r"(dst), "l"(src));
}
__device__ __forceinline__ void cp_commit() {
    asm volatile("cp.async.commit_group;" ::: "memory");
}
__device__ __forceinline__ void cp_wait2() {
    asm volatile("cp.async.wait_group 2;" ::: "memory");
}
__device__ __forceinline__ void split_bf16(float v, __nv_bfloat16& hi, __nv_bfloat16& lo) {
    hi = __float2bfloat16(v);
    lo = __float2bfloat16(v - __bfloat162float(hi));
}

// ---------------------------------------------------------------------------
// Conversion: f32 [rows, K] -> bf16 hi/lo split [rows, 3K].
// ---------------------------------------------------------------------------
template <int DSTSEL, int IS_W, int K>
__global__ __launch_bounds__(256)
void conv_kernel(const float* __restrict__ src, int row_base)
{
    __nv_bfloat16* dst = (DSTSEL == 0) ? g_x3 : (DSTSEL == 1) ? g_wg3
                       : (DSTSEL == 2) ? g_wc3 : g_wo3;
    const size_t i = (size_t)blockIdx.x * 256 + threadIdx.x;
    const float4 v = ((const float4*)src)[i];
    const size_t e = i * 4;
    const size_t row = e / K;
    const int k = (int)(e - row * K);

    const float f[4] = { v.x, v.y, v.z, v.w };
    __nv_bfloat16 hi[4], lo[4];
#pragma unroll
    for (int j = 0; j < 4; j++) split_bf16(f[j], hi[j], lo[j]);

    __nv_bfloat16* base = dst + (row_base + row) * (size_t)(3 * K) + k;
    *(uint2*)(base)         = *(const uint2*)hi;
    *(uint2*)(base + K)     = IS_W ? *(const uint2*)hi : *(const uint2*)lo;
    *(uint2*)(base + 2 * K) = IS_W ? *(const uint2*)lo : *(const uint2*)hi;
}

// ---------------------------------------------------------------------------
// Pipelined warp-MMA bf16 GEMM, 512 threads (16 warps, 4/SMSP).
//   MODE 0: g_uv (ldc 512); MODE 1: g_h = acc+(D+1)*X (ldc 1024);
//   MODE 2: C_ext = acc + bias (ldc 1024)
// grid = (Nsz/BN, M/BM)
// ---------------------------------------------------------------------------
template <int MODE>
__global__ __launch_bounds__(512, 1)
void tgemm(float* __restrict__ C_ext, const float* __restrict__ bias,
           const float* __restrict__ X, const float* __restrict__ Dv, int K3)
{
    extern __shared__ __align__(128) char smem[];
    const uint32_t sb = cvta_smem(smem);

    const __nv_bfloat16* A = (MODE == 0) ? g_x3  : (MODE == 1) ? g_s3  : g_hn3;
    const __nv_bfloat16* W = (MODE == 0) ? g_wg3 : (MODE == 1) ? g_wc3 : g_wo3;
    float* C = (MODE == 0) ? g_uv : (MODE == 1) ? g_h : C_ext;
    const int ldc = (MODE == 0) ? 512 : 1024;

    const int tid = threadIdx.x, lane = tid & 31, wid = tid >> 5;
    const int wm = wid & 1, wn = wid >> 1;          // 2 x 8 warp grid (64x32 tiles)
    const int m0 = blockIdx.y * BM, n0 = blockIdx.x * BN;

    // cp.async mapping: 512 threads; A = 1 round (128 rows), B = 2 rounds (256)
    const int grow = tid >> 2;            // 0..127
    const int gseg = tid & 3;
    const __nv_bfloat16* Ag = A + (size_t)(m0 + grow) * K3 + gseg * 8;
    const __nv_bfloat16* Wg = W + (size_t)(n0 + grow) * K3 + gseg * 8;
    const size_t w128 = (size_t)128 * K3;
    const uint32_t aDst = sb + (grow * ASTR + gseg * 8) * 2;
    const uint32_t bDst = sb + A_STAGE_B + (grow * ASTR + gseg * 8) * 2;
    const uint32_t bDst2 = bDst + 128 * ASTR * 2;

    const int NKT = K3 >> 5;

    auto issue = [&](int s, int kt) {
        const uint32_t so = (uint32_t)(s * STAGE_B);
        const size_t ko = (size_t)kt * 32;
        cpasync16(aDst + so, Ag + ko);
        cpasync16(bDst + so, Wg + ko);
        cpasync16(bDst2 + so, Wg + w128 + ko);
    };

#pragma unroll
    for (int s = 0; s < 3; s++) { issue(s, s); cp_commit(); }

    float acc[4][4][4];
#pragma unroll
    for (int i = 0; i < 4; i++)
#pragma unroll
        for (int j = 0; j < 4; j++)
#pragma unroll
            for (int q = 0; q < 4; q++) acc[i][j][q] = 0.f;

    const int lrow = lane & 15;
    const int lcol = (lane >> 4) << 3;
    const uint32_t aBase = sb + ((wm * 64 + lrow) * ASTR + lcol) * 2;
    const uint32_t bBase = sb + A_STAGE_B + ((wn * 32 + lrow) * ASTR + lcol) * 2;

    for (int kt = 0; kt < NKT; kt++) {
        cp_wait2();
        __syncthreads();
        if (kt + 3 < NKT) issue((kt + 3) & 3, kt + 3);
        cp_commit();

        const uint32_t so = (uint32_t)((kt & 3) * STAGE_B);
        const uint32_t aS = aBase + so;
        const uint32_t bS = bBase + so;
#pragma unroll
        for (int h = 0; h < 2; h++) {
            uint32_t a[4][4], b[4][2];
#pragma unroll
            for (int i = 0; i < 4; i++)
                ldsm4(a[i][0], a[i][1], a[i][2], a[i][3],
                      aS + (i * 16 * ASTR + h * 16) * 2);
#pragma unroll
            for (int jj = 0; jj < 2; jj++) {
                uint32_t r0, r1, r2, r3;
                ldsm4(r0, r1, r2, r3, bS + (jj * 16 * ASTR + h * 16) * 2);
                b[2 * jj][0] = r0;     b[2 * jj][1] = r2;
                b[2 * jj + 1][0] = r1; b[2 * jj + 1][1] = r3;
            }
#pragma unroll
            for (int i = 0; i < 4; i++)
#pragma unroll
                for (int j = 0; j < 4; j++)
                    mma16816(acc[i][j], a[i], b[j]);
        }
    }

    // epilogue
#pragma unroll
    for (int i = 0; i < 4; i++) {
        const int r = m0 + wm * 64 + i * 16 + (lane >> 2);
#pragma unroll
        for (int j = 0; j < 4; j++) {
            const int c = n0 + wn * 32 + j * 8 + (lane & 3) * 2;
            float2 v0 = make_float2(acc[i][j][0], acc[i][j][1]);
            float2 v1 = make_float2(acc[i][j][2], acc[i][j][3]);
            if (MODE == 1) {
                const float2 dv = *(const float2*)(Dv + c);
                const float2 x0 = *(const float2*)(X + (size_t)r * 1024 + c);
                const float2 x1 = *(const float2*)(X + (size_t)(r + 8) * 1024 + c);
                v0.x += (dv.x + 1.0f) * x0.x;  v0.y += (dv.y + 1.0f) * x0.y;
                v1.x += (dv.x + 1.0f) * x1.x;  v1.y += (dv.y + 1.0f) * x1.y;
            } else if (MODE == 2) {
                const float2 bv = *(const float2*)(bias + c);
                v0.x += bv.x; v0.y += bv.y;
                v1.x += bv.x; v1.y += bv.y;
            }
            *(float2*)&C[(size_t)r * ldc + c]       = v0;
            *(float2*)&C[(size_t)(r + 8) * ldc + c] = v1;
        }
    }
}

// ---------------------------------------------------------------------------
// Fused gate + scan + state split -> g_s3 (hi|lo|hi), final_state
// ---------------------------------------------------------------------------
__global__ __launch_bounds__(256)
void scan_kernel(const float* __restrict__ state0,
                 const float* __restrict__ A_log,
                 const float* __restrict__ gate_b,
                 float* __restrict__ final_state)
{
    const int chain = blockIdx.x * 256 + threadIdx.x;
    const int b = chain >> 8;
    const int n = chain & (Nst - 1);

    float Av = expf(A_log[n]);
    Av = fminf(fmaxf(Av, 0.5f), 0.99f);
    const float gb = gate_b[n];

    float s = state0[b * Nst + n];
    const float* uvp = g_uv + (size_t)b * Ss * 512 + n;
    __nv_bfloat16* sp = g_s3 + (size_t)b * Ss * (3 * Nst) + n;

#pragma unroll 4
    for (int t = 0; t < Ss; t++) {
        const float gl = uvp[(size_t)t * 512] + gb;
        const float ub = uvp[(size_t)t * 512 + 256];
        float sg = 1.0f / (1.0f + expf(-gl));
        sg = fminf(fmaxf(sg, 0.0f), 1.0f);
        s = fminf(fmaxf(fmaf(Av, s, sg * ub), -10.0f), 10.0f);
        __nv_bfloat16 hi, lo;
        split_bf16(s, hi, lo);
        sp[(size_t)t * 768]       = hi;
        sp[(size_t)t * 768 + 256] = lo;
        sp[(size_t)t * 768 + 512] = hi;
    }
    final_state[b * Nst + n] = s;
}

// ---------------------------------------------------------------------------
// LayerNorm (single pass, shuffle reductions) + hi/lo split -> g_hn3
// ---------------------------------------------------------------------------
__global__ __launch_bounds__(256)
void ln_kernel(const float* __restrict__ g, const float* __restrict__ bta)
{
    __shared__ float psum[8], psq[8], bcast[2];
    const int row = blockIdx.x;
    const int t = threadIdx.x;
    const int lane = t & 31, wd = t >> 5;
    const float* hp = g_h + (size_t)row * Hh;

    float4 v = *(const float4*)(hp + (t << 2));
    float sm = v.x + v.y + v.z + v.w;
    float sq = v.x * v.x + v.y * v.y + v.z * v.z + v.w * v.w;

#pragma unroll
    for (int off = 16; off; off >>= 1) {
        sm += __shfl_xor_sync(0xffffffffu, sm, off);
        sq += __shfl_xor_sync(0xffffffffu, sq, off);
    }
    if (lane == 0) { psum[wd] = sm; psq[wd] = sq; }
    __syncthreads();
    if (wd == 0) {
        float a = (lane < 8) ? psum[lane] : 0.f;
        float b = (lane < 8) ? psq[lane] : 0.f;
#pragma unroll
        for (int off = 4; off; off >>= 1) {
            a += __shfl_xor_sync(0xffffffffu, a, off);
            b += __shfl_xor_sync(0xffffffffu, b, off);
        }
        if (lane == 0) {
            const float mu = a * (1.0f / Hh);
            const float var = b * (1.0f / Hh) - mu * mu;
            bcast[0] = mu;
            bcast[1] = rsqrtf(var + 1e-5f);
        }
    }
    __syncthreads();
    const float mu = bcast[0], inv = bcast[1];

    const int c = t << 2;
    float o[4];
    o[0] = (v.x - mu) * inv * g[c + 0] + bta[c + 0];
    o[1] = (v.y - mu) * inv * g[c + 1] + bta[c + 1];
    o[2] = (v.z - mu) * inv * g[c + 2] + bta[c + 2];
    o[3] = (v.w - mu) * inv * g[c + 3] + bta[c + 3];

    __nv_bfloat16 hi[4], lo[4];
#pragma unroll
    for (int j = 0; j < 4; j++) split_bf16(o[j], hi[j], lo[j]);

    __nv_bfloat16* base = g_hn3 + (size_t)row * (3 * Hh) + c;
    *(uint2*)(base)          = *(const uint2*)hi;
    *(uint2*)(base + Hh)     = *(const uint2*)lo;
    *(uint2*)(base + 2 * Hh) = *(const uint2*)hi;
}

// ---------------------------------------------------------------------------
// Launch
// ---------------------------------------------------------------------------
extern "C" void kernel_launch(void* const* d_in, const int* in_sizes, int n_in,
                              void* d_out, int out_size)
{
    const float* x      = (const float*)d_in[0];
    const float* state0 = (const float*)d_in[1];
    const float* A_log  = (const float*)d_in[2];
    const float* B_w    = (const float*)d_in[3];
    const float* C_w    = (const float*)d_in[4];
    const float* Dv     = (const float*)d_in[5];
    const float* gate_w = (const float*)d_in[6];
    const float* gate_b = (const float*)d_in[7];
    const float* out_w  = (const float*)d_in[8];
    const float* out_b  = (const float*)d_in[9];
    const float* ln_g   = (const float*)d_in[10];
    const float* ln_b   = (const float*)d_in[11];

    float* out = (float*)d_out;
    float* final_state = out + (size_t)Mm * Hh;

    cudaFuncSetAttribute(tgemm<0>, cudaFuncAttributeMaxDynamicSharedMemorySize, SMEM_TOTAL);
    cudaFuncSetAttribute(tgemm<1>, cudaFuncAttributeMaxDynamicSharedMemorySize, SMEM_TOTAL);
    cudaFuncSetAttribute(tgemm<2>, cudaFuncAttributeMaxDynamicSharedMemorySize, SMEM_TOTAL);

    // 1) conversions
    conv_kernel<0, 0, 1024><<<Mm, 256>>>(x, 0);
    conv_kernel<1, 1, 1024><<<256, 256>>>(gate_w, 0);
    conv_kernel<1, 1, 1024><<<256, 256>>>(B_w, 256);

    // 2) GEMM0: g_uv[16384, 512]   (K3 = 3072)
    tgemm<0><<<dim3(512 / BN, Mm / BM), 512, SMEM_TOTAL>>>(
        nullptr, nullptr, nullptr, nullptr, 3 * Hh);

    // 3) fused gate + scan + split
    scan_kernel<<<(Bb * Nst) / 256, 256>>>(state0, A_log, gate_b, final_state);

    // 4) GEMM1: g_h = s3 @ wc3^T + (D+1)*x   (K3 = 768)
    conv_kernel<2, 1, 256><<<256, 256>>>(C_w, 0);
    tgemm<1><<<dim3(Hh / BN, Mm / BM), 512, SMEM_TOTAL>>>(
        nullptr, nullptr, x, Dv, 3 * Nst);

    // 5) LN + split
    ln_kernel<<<Mm, 256>>>(ln_g, ln_b);

    // 6) GEMM2: out = hn3 @ wo3^T + out_b    (K3 = 3072)
    conv_kernel<3, 1, 1024><<<1024, 256>>>(out_w, 0);
    tgemm<2><<<dim3(Hh / BN, Mm / BM), 512, SMEM_TOTAL>>>(
        out, out_b, nullptr, nullptr, 3 * Hh);
}

// round 17
// speedup vs baseline: 1.8762x; 1.7819x over previous
#include <cuda_runtime.h>
#include <cuda_bf16.h>
#include <cstdint>
#include <cstddef>
#include <math.h>

// Problem dims
#define Bb 8
#define Ss 2048
#define Hh 1024
#define Nst 256
#define Mm (Bb * Ss)        // 16384

// GEMM tiling: CTA 128x256x32, 16 warps of 64x32, cp.async 4-stage
#define BM 128
#define BN 256
#define ASTR 40                          // smem row stride in bf16 (80 B)
#define A_STAGE_B (128 * ASTR * 2)       // 10240 B
#define B_STAGE_B (256 * ASTR * 2)       // 20480 B
#define STAGE_B   (A_STAGE_B + B_STAGE_B)// 30720 B
#define NSTG 4
#define SMEM_TOTAL (NSTG * STAGE_B)      // 122880 B

// scan staging
#define SCH 32
#define SCAN_SMEM (2 * SCH * 512 * 4)    // 131072 B

// ---------------------------------------------------------------------------
// Scratch. A-side buffers hold 2 regions [hi|lo] (row stride 2K);
// W-side buffers hold 3 regions [Wh|Wh|Wl] (row stride 3K).
// tgemm redirects A region 2 -> region 0.
// ---------------------------------------------------------------------------
__device__ __align__(256) __nv_bfloat16 g_x3 [(size_t)Mm * 2 * Hh];
__device__ __align__(256) __nv_bfloat16 g_wg3[(size_t)512 * 3 * Hh];
__device__ __align__(256) float         g_uv [(size_t)Mm * 512];
__device__ __align__(256) __nv_bfloat16 g_s3 [(size_t)Mm * 2 * Nst];
__device__ __align__(256) __nv_bfloat16 g_wc3[(size_t)Hh * 3 * Nst];
__device__ __align__(256) float         g_h  [(size_t)Mm * Hh];
__device__ __align__(256) __nv_bfloat16 g_hn3[(size_t)Mm * 2 * Hh];
__device__ __align__(256) __nv_bfloat16 g_wo3[(size_t)Hh * 3 * Hh];

// ---------------------------------------------------------------------------
// helpers
// ---------------------------------------------------------------------------
__device__ __forceinline__ uint32_t cvta_smem(const void* p) {
    uint32_t a;
    asm("{ .reg .u64 t; cvta.to.shared.u64 t, %1; cvt.u32.u64 %0, t; }"
        : "=r"(a) : "l"(p));
    return a;
}
__device__ __forceinline__ void ldsm4(uint32_t& r0, uint32_t& r1,
                                      uint32_t& r2, uint32_t& r3, uint32_t addr) {
    asm volatile("ldmatrix.sync.aligned.m8n8.x4.shared.b16 {%0,%1,%2,%3}, [%4];"
                 : "=r"(r0), "=r"(r1), "=r"(r2), "=r"(r3) : "r"(addr));
}
__device__ __forceinline__ void mma16816(float* d, const uint32_t* a, const uint32_t* b) {
    asm volatile(
        "mma.sync.aligned.m16n8k16.row.col.f32.bf16.bf16.f32 "
        "{%0,%1,%2,%3}, {%4,%5,%6,%7}, {%8,%9}, {%0,%1,%2,%3};"
        : "+f"(d[0]), "+f"(d[1]), "+f"(d[2]), "+f"(d[3])
        : "r"(a[0]), "r"(a[1]), "r"(a[2]), "r"(a[3]), "r"(b[0]), "r"(b[1]));
}
__device__ __forceinline__ void cpasync16(uint32_t dst, const void* src) {
    asm volatile("cp.async.cg.shared.global [%0], [%1], 16;"
                 :: "r"(dst), "l"(src));
}
__device__ __forceinline__ void cp_commit() {
    asm volatile("cp.async.commit_group;" ::: "memory");
}
__device__ __forceinline__ void cp_wait2() {
    asm volatile("cp.async.wait_group 2;" ::: "memory");
}
__device__ __forceinline__ void cp_wait1() {
    asm volatile("cp.async.wait_group 1;" ::: "memory");
}
// register-safe bf16x2 pack (no address-of-register-array punning)
__device__ __forceinline__ uint32_t packbf(float a, float b) {
    return (uint32_t)__bfloat16_as_ushort(__float2bfloat16(a))
         | ((uint32_t)__bfloat16_as_ushort(__float2bfloat16(b)) << 16);
}
__device__ __forceinline__ float bf_lo(float v) {
    return v - __bfloat162float(__float2bfloat16(v));
}

// ---------------------------------------------------------------------------
// Conversion: f32 [rows, K] -> bf16 split.
// IS_W = 0: dst [rows, 2K] = [hi|lo].  IS_W = 1: dst [rows, 3K] = [hi|hi|lo].
// DSTSEL: 0 g_x3, 1 g_wg3, 2 g_wc3, 3 g_wo3.
// ---------------------------------------------------------------------------
template <int DSTSEL, int IS_W, int K>
__global__ __launch_bounds__(256)
void conv_kernel(const float* __restrict__ src, int row_base)
{
    __nv_bfloat16* dst = (DSTSEL == 0) ? g_x3 : (DSTSEL == 1) ? g_wg3
                       : (DSTSEL == 2) ? g_wc3 : g_wo3;
    const size_t i = (size_t)blockIdx.x * 256 + threadIdx.x;
    const float4 v = ((const float4*)src)[i];
    const size_t e = i * 4;
    const size_t row = e / K;
    const int k = (int)(e - row * K);

    const uint2 hiv = make_uint2(packbf(v.x, v.y), packbf(v.z, v.w));
    const uint2 lov = make_uint2(packbf(bf_lo(v.x), bf_lo(v.y)),
                                 packbf(bf_lo(v.z), bf_lo(v.w)));

    const int RK = IS_W ? 3 * K : 2 * K;
    __nv_bfloat16* base = dst + (row_base + row) * (size_t)RK + k;
    if (IS_W) {
        *(uint2*)(base)         = hiv;
        *(uint2*)(base + K)     = hiv;
        *(uint2*)(base + 2 * K) = lov;
    } else {
        *(uint2*)(base)     = hiv;
        *(uint2*)(base + K) = lov;
    }
}

// ---------------------------------------------------------------------------
// Pipelined warp-MMA bf16 GEMM, 512 threads (16 warps, 4/SMSP).
// A: [rows, 2K] = [hi|lo]; W: [rows, 3K] = [Wh|Wh|Wl].
// Total kts = 3K/32; A kt redirected: ka = kt < 2K/32 ? kt : kt - 2K/32.
//   MODE 0: g_uv (ldc 512); MODE 1: g_h = acc+(D+1)*X (ldc 1024);
//   MODE 2: C_ext = acc + bias (ldc 1024)
// ---------------------------------------------------------------------------
template <int MODE>
__global__ __launch_bounds__(512, 1)
void tgemm(float* __restrict__ C_ext, const float* __restrict__ bias,
           const float* __restrict__ X, const float* __restrict__ Dv, int K)
{
    extern __shared__ __align__(128) char smem[];
    const uint32_t sb = cvta_smem(smem);

    const __nv_bfloat16* A = (MODE == 0) ? g_x3  : (MODE == 1) ? g_s3  : g_hn3;
    const __nv_bfloat16* W = (MODE == 0) ? g_wg3 : (MODE == 1) ? g_wc3 : g_wo3;
    float* C = (MODE == 0) ? g_uv : (MODE == 1) ? g_h : C_ext;
    const int ldc = (MODE == 0) ? 512 : 1024;

    const int KA = 2 * K, KW = 3 * K;
    const int NKT = KW >> 5;          // total k-chunks
    const int KT2 = KA >> 5;          // A redirect threshold

    const int tid = threadIdx.x, lane = tid & 31, wid = tid >> 5;
    const int wm = wid & 1, wn = wid >> 1;          // 2 x 8 warp grid (64x32)
    const int m0 = blockIdx.y * BM, n0 = blockIdx.x * BN;

    const int grow = tid >> 2;            // 0..127
    const int gseg = tid & 3;
    const __nv_bfloat16* Ag = A + (size_t)(m0 + grow) * KA + gseg * 8;
    const __nv_bfloat16* Wg = W + (size_t)(n0 + grow) * KW + gseg * 8;
    const size_t w128 = (size_t)128 * KW;
    const uint32_t aDst = sb + (grow * ASTR + gseg * 8) * 2;
    const uint32_t bDst = sb + A_STAGE_B + (grow * ASTR + gseg * 8) * 2;
    const uint32_t bDst2 = bDst + 128 * ASTR * 2;

    auto issue = [&](int s, int kt) {
        const uint32_t so = (uint32_t)(s * STAGE_B);
        const int ka = (kt < KT2) ? kt : kt - KT2;
        cpasync16(aDst + so, Ag + (size_t)ka * 32);
        const size_t ko = (size_t)kt * 32;
        cpasync16(bDst + so, Wg + ko);
        cpasync16(bDst2 + so, Wg + w128 + ko);
    };

#pragma unroll
    for (int s = 0; s < 3; s++) { issue(s, s); cp_commit(); }

    float acc[4][4][4];
#pragma unroll
    for (int i = 0; i < 4; i++)
#pragma unroll
        for (int j = 0; j < 4; j++)
#pragma unroll
            for (int q = 0; q < 4; q++) acc[i][j][q] = 0.f;

    const int lrow = lane & 15;
    const int lcol = (lane >> 4) << 3;
    const uint32_t aBase = sb + ((wm * 64 + lrow) * ASTR + lcol) * 2;
    const uint32_t bBase = sb + A_STAGE_B + ((wn * 32 + lrow) * ASTR + lcol) * 2;

    for (int kt = 0; kt < NKT; kt++) {
        cp_wait2();
        __syncthreads();
        if (kt + 3 < NKT) issue((kt + 3) & 3, kt + 3);
        cp_commit();

        const uint32_t so = (uint32_t)((kt & 3) * STAGE_B);
        const uint32_t aS = aBase + so;
        const uint32_t bS = bBase + so;
#pragma unroll
        for (int h = 0; h < 2; h++) {
            uint32_t a[4][4], b[4][2];
#pragma unroll
            for (int i = 0; i < 4; i++)
                ldsm4(a[i][0], a[i][1], a[i][2], a[i][3],
                      aS + (i * 16 * ASTR + h * 16) * 2);
#pragma unroll
            for (int jj = 0; jj < 2; jj++) {
                uint32_t r0, r1, r2, r3;
                ldsm4(r0, r1, r2, r3, bS + (jj * 16 * ASTR + h * 16) * 2);
                b[2 * jj][0] = r0;     b[2 * jj][1] = r2;
                b[2 * jj + 1][0] = r1; b[2 * jj + 1][1] = r3;
            }
#pragma unroll
            for (int i = 0; i < 4; i++)
#pragma unroll
                for (int j = 0; j < 4; j++)
                    mma16816(acc[i][j], a[i], b[j]);
        }
    }

    // epilogue
#pragma unroll
    for (int i = 0; i < 4; i++) {
        const int r = m0 + wm * 64 + i * 16 + (lane >> 2);
#pragma unroll
        for (int j = 0; j < 4; j++) {
            const int c = n0 + wn * 32 + j * 8 + (lane & 3) * 2;
            float2 v0 = make_float2(acc[i][j][0], acc[i][j][1]);
            float2 v1 = make_float2(acc[i][j][2], acc[i][j][3]);
            if (MODE == 1) {
                const float2 dv = *(const float2*)(Dv + c);
                const float2 x0 = *(const float2*)(X + (size_t)r * 1024 + c);
                const float2 x1 = *(const float2*)(X + (size_t)(r + 8) * 1024 + c);
                v0.x += (dv.x + 1.0f) * x0.x;  v0.y += (dv.y + 1.0f) * x0.y;
                v1.x += (dv.x + 1.0f) * x1.x;  v1.y += (dv.y + 1.0f) * x1.y;
            } else if (MODE == 2) {
                const float2 bv = *(const float2*)(bias + c);
                v0.x += bv.x; v0.y += bv.y;
                v1.x += bv.x; v1.y += bv.y;
            }
            *(float2*)&C[(size_t)r * ldc + c]       = v0;
            *(float2*)&C[(size_t)(r + 8) * ldc + c] = v1;
        }
    }
}

// ---------------------------------------------------------------------------
// smem-staged fused gate + scan + split. grid = Bb blocks, 256 threads.
// cp.async double-buffers SCH-timestep chunks of g_uv (2 KB/row).
// Writes g_s3 [b*Ss + t][hi|lo] (row stride 512) and final_state.
// ---------------------------------------------------------------------------
__global__ __launch_bounds__(256)
void scan_kernel(const float* __restrict__ state0,
                 const float* __restrict__ A_log,
                 const float* __restrict__ gate_b,
                 float* __restrict__ final_state)
{
    extern __shared__ __align__(16) float sbuf[];   // [2][SCH][512]
    const int b = blockIdx.x;
    const int n = threadIdx.x;

    float Av = expf(A_log[n]);
    Av = fminf(fmaxf(Av, 0.5f), 0.99f);
    const float gb = gate_b[n];
    float s = state0[b * Nst + n];

    const float4* usrc = (const float4*)(g_uv + (size_t)b * Ss * 512);
    const uint32_t sbase = cvta_smem(sbuf);

    auto issue = [&](int c) {
        const uint32_t dst0 = sbase + (uint32_t)((c & 1) * SCH * 512 * 4);
        const float4* src = usrc + (size_t)c * SCH * 128;
#pragma unroll
        for (int i = 0; i < 16; i++) {
            const int idx = i * 256 + n;
            cpasync16(dst0 + idx * 16, src + idx);
        }
    };

    issue(0); cp_commit();
    issue(1); cp_commit();

    __nv_bfloat16* sp = g_s3 + (size_t)b * Ss * 512 + n;
    const int NCH = Ss / SCH;     // 64

    for (int c = 0; c < NCH; c++) {
        cp_wait1();
        __syncthreads();
        const float* bp = sbuf + (c & 1) * SCH * 512;
        __nv_bfloat16* spc = sp + (size_t)c * SCH * 512;
#pragma unroll 8
        for (int t = 0; t < SCH; t++) {
            const float gl = bp[t * 512 + n] + gb;
            const float ub = bp[t * 512 + 256 + n];
            float sg = 1.0f / (1.0f + expf(-gl));
            sg = fminf(fmaxf(sg, 0.0f), 1.0f);
            s = fminf(fmaxf(fmaf(Av, s, sg * ub), -10.0f), 10.0f);
            const __nv_bfloat16 hi = __float2bfloat16(s);
            spc[(size_t)t * 512]       = hi;
            spc[(size_t)t * 512 + 256] = __float2bfloat16(s - __bfloat162float(hi));
        }
        __syncthreads();
        if (c + 2 < NCH) { issue(c + 2); cp_commit(); }
    }
    final_state[b * Nst + n] = s;
}

// ---------------------------------------------------------------------------
// LayerNorm (single pass, shuffle reductions) + hi/lo split -> g_hn3 [row, 2H]
// ---------------------------------------------------------------------------
__global__ __launch_bounds__(256)
void ln_kernel(const float* __restrict__ g, const float* __restrict__ bta)
{
    __shared__ float psum[8], psq[8], bcast[2];
    const int row = blockIdx.x;
    const int t = threadIdx.x;
    const int lane = t & 31, wd = t >> 5;
    const float* hp = g_h + (size_t)row * Hh;

    float4 v = *(const float4*)(hp + (t << 2));
    float sm = v.x + v.y + v.z + v.w;
    float sq = v.x * v.x + v.y * v.y + v.z * v.z + v.w * v.w;

#pragma unroll
    for (int off = 16; off; off >>= 1) {
        sm += __shfl_xor_sync(0xffffffffu, sm, off);
        sq += __shfl_xor_sync(0xffffffffu, sq, off);
    }
    if (lane == 0) { psum[wd] = sm; psq[wd] = sq; }
    __syncthreads();
    if (wd == 0) {
        float a = (lane < 8) ? psum[lane] : 0.f;
        float b = (lane < 8) ? psq[lane] : 0.f;
#pragma unroll
        for (int off = 4; off; off >>= 1) {
            a += __shfl_xor_sync(0xffffffffu, a, off);
            b += __shfl_xor_sync(0xffffffffu, b, off);
        }
        if (lane == 0) {
            const float mu = a * (1.0f / Hh);
            const float var = b * (1.0f / Hh) - mu * mu;
            bcast[0] = mu;
            bcast[1] = rsqrtf(var + 1e-5f);
        }
    }
    __syncthreads();
    const float mu = bcast[0], inv = bcast[1];

    const int c = t << 2;
    float o[4];
    o[0] = (v.x - mu) * inv * g[c + 0] + bta[c + 0];
    o[1] = (v.y - mu) * inv * g[c + 1] + bta[c + 1];
    o[2] = (v.z - mu) * inv * g[c + 2] + bta[c + 2];
    o[3] = (v.w - mu) * inv * g[c + 3] + bta[c + 3];

    __nv_bfloat16* base = g_hn3 + (size_t)row * (2 * Hh) + c;
    *(uint2*)(base)      = make_uint2(packbf(o[0], o[1]), packbf(o[2], o[3]));
    *(uint2*)(base + Hh) = make_uint2(packbf(bf_lo(o[0]), bf_lo(o[1])),
                                      packbf(bf_lo(o[2]), bf_lo(o[3])));
}

// ---------------------------------------------------------------------------
// Launch
// ---------------------------------------------------------------------------
extern "C" void kernel_launch(void* const* d_in, const int* in_sizes, int n_in,
                              void* d_out, int out_size)
{
    const float* x      = (const float*)d_in[0];
    const float* state0 = (const float*)d_in[1];
    const float* A_log  = (const float*)d_in[2];
    const float* B_w    = (const float*)d_in[3];
    const float* C_w    = (const float*)d_in[4];
    const float* Dv     = (const float*)d_in[5];
    const float* gate_w = (const float*)d_in[6];
    const float* gate_b = (const float*)d_in[7];
    const float* out_w  = (const float*)d_in[8];
    const float* out_b  = (const float*)d_in[9];
    const float* ln_g   = (const float*)d_in[10];
    const float* ln_b   = (const float*)d_in[11];

    float* out = (float*)d_out;
    float* final_state = out + (size_t)Mm * Hh;

    cudaFuncSetAttribute(tgemm<0>, cudaFuncAttributeMaxDynamicSharedMemorySize, SMEM_TOTAL);
    cudaFuncSetAttribute(tgemm<1>, cudaFuncAttributeMaxDynamicSharedMemorySize, SMEM_TOTAL);
    cudaFuncSetAttribute(tgemm<2>, cudaFuncAttributeMaxDynamicSharedMemorySize, SMEM_TOTAL);
    cudaFuncSetAttribute(scan_kernel, cudaFuncAttributeMaxDynamicSharedMemorySize, SCAN_SMEM);

    // 1) conversions
    conv_kernel<0, 0, 1024><<<Mm, 256>>>(x, 0);
    conv_kernel<1, 1, 1024><<<256, 256>>>(gate_w, 0);
    conv_kernel<1, 1, 1024><<<256, 256>>>(B_w, 256);

    // 2) GEMM0: g_uv[16384, 512]   (K = 1024)
    tgemm<0><<<dim3(512 / BN, Mm / BM), 512, SMEM_TOTAL>>>(
        nullptr, nullptr, nullptr, nullptr, Hh);

    // 3) smem-staged gate + scan + split
    scan_kernel<<<Bb, 256, SCAN_SMEM>>>(state0, A_log, gate_b, final_state);

    // 4) GEMM1: g_h = s3 @ wc3^T + (D+1)*x   (K = 256)
    conv_kernel<2, 1, 256><<<256, 256>>>(C_w, 0);
    tgemm<1><<<dim3(Hh / BN, Mm / BM), 512, SMEM_TOTAL>>>(
        nullptr, nullptr, x, Dv, Nst);

    // 5) LN + split
    ln_kernel<<<Mm, 256>>>(ln_g, ln_b);

    // 6) GEMM2: out = hn3 @ wo3^T + out_b    (K = 1024)
    conv_kernel<3, 1, 1024><<<1024, 256>>>(out_w, 0);
    tgemm<2><<<dim3(Hh / BN, Mm / BM), 512, SMEM_TOTAL>>>(
        out, out_b, nullptr, nullptr, Hh);
}